// round 16
// baseline (speedup 1.0000x reference)
#include <cuda_runtime.h>
#include <cstdint>

#define NQ      14
#define NSTATE  (1 << NQ)          // 16384
#define NLAYERS 6
#define NGATES  (NLAYERS * NQ)     // 84 (RX merged into layer-0 Rot)
#define NPASSES ((NLAYERS - 1) * 3)  // 15: layers 1..5, per layer 2x NW=5(split) + 1x NW=4
#define TPB     512

typedef unsigned long long ull;
typedef unsigned u32;

struct PassP {
    u32 cmb[32];        // byte-scaled slot XOR masks (cm[j]<<2), logical 5-bit index
    u32 r[5];           // parity rows (L^-1), in pass gate order
    u32 f;              // duo-lane1 orientation flip bits (r_k . e_d); bit4==0 for split
    u32 ddb;            // byte-scaled duo offset (4 << d)
    unsigned char Arl[8];  // stagger relabel index per lane bit (Arl[0]==0 for split)
    signed   char ep[8];   // sorted insert positions: nw pivots + duo bit d
    unsigned char g[8];    // gate ids (nw used)
    int nw;             // 5 (split across thread pairs) or 4
};
struct Params { PassP p[NPASSES]; u32 rz; };

// ---------------- packed f32x2 helpers ----------------
__device__ __forceinline__ ull pack2f(float lo, float hi) {
    ull r; asm("mov.b64 %0,{%1,%2};" : "=l"(r) : "f"(lo), "f"(hi)); return r;
}
__device__ __forceinline__ void unpack2f(ull v, float& lo, float& hi) {
    asm("mov.b64 {%0,%1},%2;" : "=f"(lo), "=f"(hi) : "l"(v));
}
__device__ __forceinline__ ull ffma2(ull a, ull b, ull c) {
    ull d; asm("fma.rn.f32x2 %0,%1,%2,%3;" : "=l"(d) : "l"(a), "l"(b), "l"(c)); return d;
}
__device__ __forceinline__ ull fmul2(ull a, ull b) {
    ull d; asm("mul.rn.f32x2 %0,%1,%2;" : "=l"(d) : "l"(a), "l"(b)); return d;
}
__device__ __forceinline__ ull neg2(ull a) {
    return a ^ 0x8000000080000000ull;
}

// ---------------- raw shared ld/st (32-bit address space) ----------------
__device__ __forceinline__ float ldsf(u32 a) {
    float v; asm volatile("ld.shared.f32 %0,[%1];" : "=f"(v) : "r"(a)); return v;
}
__device__ __forceinline__ float ldsfI(u32 a) {
    float v; asm volatile("ld.shared.f32 %0,[%1+65536];" : "=f"(v) : "r"(a)); return v;
}
__device__ __forceinline__ void stsf(u32 a, float v) {
    asm volatile("st.shared.f32 [%0],%1;" :: "r"(a), "f"(v));
}
__device__ __forceinline__ void stsfI(u32 a, float v) {
    asm volatile("st.shared.f32 [%0+65536],%1;" :: "r"(a), "f"(v));
}

// 7-coeff expanded gate, built once per gate, zero negs per su2duo
struct PGd7 { ull pax, pu, pnu, pv, pnv, pw, pnw; };

// duo SU(2), SoA lanes = two independent groups.  u=ay, v=bx, w=by.
__device__ __forceinline__ void su2duo7(const PGd7& g, ull& ra, ull& ia, ull& rb, ull& ib) {
    ull nra = ffma2(g.pax, ra, ffma2(g.pnu, ia, ffma2(g.pnv, rb, fmul2(g.pnw, ib))));
    ull nia = ffma2(g.pax, ia, ffma2(g.pu,  ra, ffma2(g.pnv, ib, fmul2(g.pw,  rb))));
    ull nrb = ffma2(g.pax, rb, ffma2(g.pu,  ib, ffma2(g.pv,  ra, fmul2(g.pnw, ia))));
    ull nib = ffma2(g.pax, ib, ffma2(g.pnu, rb, ffma2(g.pv,  ia, fmul2(g.pw,  ra))));
    ra = nra; ia = nia; rb = nrb; ib = nib;
}

__device__ __forceinline__ constexpr int ctzc(int t) {
    return (t & 1) ? 0 : (t & 2) ? 1 : (t & 4) ? 2 : 3;
}

// build a 7-coeff gate with per-duo-lane flips folded
__device__ __forceinline__ PGd7 mk_g7(float4 gg, u32 fl0, u32 fl1) {
    float u0 = fl0 ? -gg.y : gg.y, u1 = fl1 ? -gg.y : gg.y;
    float v0 = fl0 ? -gg.z : gg.z, v1 = fl1 ? -gg.z : gg.z;
    PGd7 g;
    g.pax = pack2f(gg.x, gg.x);
    g.pu  = pack2f(u0, u1);  g.pnu = neg2(g.pu);
    g.pv  = pack2f(v0, v1);  g.pnv = neg2(g.pv);
    g.pw  = pack2f(gg.w, gg.w); g.pnw = neg2(g.pw);
    return g;
}

// ---------------- NW=4 pass, unsplit: 512 threads x 16 duo-slots ----------------
__device__ __forceinline__ void apply_pass4(u32 sbase, const float4* gates4,
                                            const PassP& pp, int tid) {
    const u32 lane = (u32)tid & 31u;
    u32 rl = 0, cofsb = 0;
    #pragma unroll
    for (int b = 0; b < 5; b++)
        if ((lane >> b) & 1u) { rl ^= pp.Arl[b]; cofsb ^= pp.cmb[pp.Arl[b]]; }

    u32 p = (u32)tid;
    #pragma unroll
    for (int i = 0; i < 5; i++) {
        int bp = pp.ep[i];
        p = ((p >> bp) << (bp + 1)) | (p & ((1u << bp) - 1u));
    }
    #pragma unroll
    for (int k = 0; k < 4; k++) {
        u32 s = (u32)(-(int)(__popc(p & pp.r[k]) & 1));
        p ^= s & (pp.cmb[1u << k] >> 2);
    }
    u32 off = (p << 2) ^ cofsb;
    u32 dg[4] = {pp.cmb[1], pp.cmb[2], pp.cmb[4], pp.cmb[8]};
    const u32 ddb = pp.ddb;

    ull vre[16], vim[16];
    {
        u32 o = off;
        #pragma unroll
        for (int t = 0; t < 16; t++) {
            if (t) o ^= dg[ctzc(t)];
            int j = t ^ (t >> 1);
            u32 a0 = sbase + o, a1 = sbase + (o ^ ddb);
            vre[j] = pack2f(ldsf(a0),  ldsf(a1));
            vim[j] = pack2f(ldsfI(a0), ldsfI(a1));
        }
    }
    #pragma unroll
    for (int k = 0; k < 4; k++) {
        float4 gg = gates4[pp.g[k]];
        u32 fl0 = (rl >> k) & 1u;
        PGd7 g7 = mk_g7(gg, fl0, fl0 ^ ((pp.f >> k) & 1u));
        #pragma unroll
        for (int j = 0; j < 16; j++) {
            if ((j >> k) & 1) continue;
            su2duo7(g7, vre[j], vim[j], vre[j | (1 << k)], vim[j | (1 << k)]);
        }
    }
    {
        u32 o = off;
        #pragma unroll
        for (int t = 0; t < 16; t++) {
            if (t) o ^= dg[ctzc(t)];
            int j = t ^ (t >> 1);
            u32 a0 = sbase + o, a1 = sbase + (o ^ ddb);
            float x0, x1, y0, y1;
            unpack2f(vre[j], x0, x1);
            unpack2f(vim[j], y0, y1);
            stsf(a0, x0);  stsf(a1, x1);
            stsfI(a0, y0); stsfI(a1, y1);
        }
    }
}

// ---------------- NW=5 pass, split across thread pairs (t, t^1) ----------------
// Thread holds 16 of the 32 duo-slots; 4 gates local, the 5th (g[4]) via SHFL.
// Host guarantees: f bit4 == 0, Arl[0] == 0.
__device__ __forceinline__ void apply_pass5s(u32 sbase, const float4* gates4,
                                             const PassP& pp, int tid) {
    const u32 lane = (u32)tid & 31u;
    const u32 role = (u32)tid & 1u;
    u32 rl = 0, cofsb = 0;
    #pragma unroll
    for (int b = 0; b < 5; b++)
        if ((lane >> b) & 1u) { rl ^= pp.Arl[b]; cofsb ^= pp.cmb[pp.Arl[b]]; }
    if (role) cofsb ^= pp.cmb[16];            // role selects logical-bit4 half
    const u32 myb4 = role ^ ((rl >> 4) & 1u); // which row of gate 4 this thread owns

    u32 p = (u32)tid >> 1;                    // duo id (256 duos)
    #pragma unroll
    for (int i = 0; i < 6; i++) {
        int bp = pp.ep[i];
        p = ((p >> bp) << (bp + 1)) | (p & ((1u << bp) - 1u));
    }
    #pragma unroll
    for (int k = 0; k < 5; k++) {
        u32 s = (u32)(-(int)(__popc(p & pp.r[k]) & 1));
        p ^= s & (pp.cmb[1u << k] >> 2);
    }
    u32 off = (p << 2) ^ cofsb;
    u32 dg[4] = {pp.cmb[1], pp.cmb[2], pp.cmb[4], pp.cmb[8]};
    const u32 ddb = pp.ddb;

    ull vre[16], vim[16];
    {
        u32 o = off;
        #pragma unroll
        for (int t = 0; t < 16; t++) {
            if (t) o ^= dg[ctzc(t)];
            int j = t ^ (t >> 1);
            u32 a0 = sbase + o, a1 = sbase + (o ^ ddb);
            vre[j] = pack2f(ldsf(a0),  ldsf(a1));
            vim[j] = pack2f(ldsfI(a0), ldsfI(a1));
        }
    }
    // local gates 0..3
    #pragma unroll
    for (int k = 0; k < 4; k++) {
        float4 gg = gates4[pp.g[k]];
        u32 fl0 = (rl >> k) & 1u;
        PGd7 g7 = mk_g7(gg, fl0, fl0 ^ ((pp.f >> k) & 1u));
        #pragma unroll
        for (int j = 0; j < 16; j++) {
            if ((j >> k) & 1) continue;
            su2duo7(g7, vre[j], vim[j], vre[j | (1 << k)], vim[j | (1 << k)]);
        }
    }
    // split gate g[4] with partner lane^1:
    // myb4==0: v' = a*v - conj(b)*vp ; myb4==1: v' = conj(a)*v + b*vp
    // unified: c1 = ax + i*s*u, c2 = -s*v + i*w,  s = +1 (myb4=0) / -1 (myb4=1)
    {
        float4 gg = gates4[pp.g[4]];
        float s    = myb4 ? -1.f : 1.f;
        float su_  = s * gg.y;
        float nsv_ = -s * gg.z;
        ull pax  = pack2f(gg.x, gg.x);
        ull psu  = pack2f(su_, su_);   ull pnsu = neg2(psu);
        ull pnsv = pack2f(nsv_, nsv_);
        ull pw   = pack2f(gg.w, gg.w); ull pnw  = neg2(pw);
        #pragma unroll
        for (int j = 0; j < 16; j++) {
            ull rep = __shfl_xor_sync(0xFFFFFFFFu, vre[j], 1);
            ull imp = __shfl_xor_sync(0xFFFFFFFFu, vim[j], 1);
            ull nre = ffma2(pax, vre[j], ffma2(pnsu, vim[j], ffma2(pnsv, rep, fmul2(pnw, imp))));
            ull nim = ffma2(pax, vim[j], ffma2(psu,  vre[j], ffma2(pnsv, imp, fmul2(pw,  rep))));
            vre[j] = nre; vim[j] = nim;
        }
    }
    {
        u32 o = off;
        #pragma unroll
        for (int t = 0; t < 16; t++) {
            if (t) o ^= dg[ctzc(t)];
            int j = t ^ (t >> 1);
            u32 a0 = sbase + o, a1 = sbase + (o ^ ddb);
            float x0, x1, y0, y1;
            unpack2f(vre[j], x0, x1);
            unpack2f(vim[j], y0, y1);
            stsf(a0, x0);  stsf(a1, x1);
            stsfI(a0, y0); stsfI(a1, y1);
        }
    }
}

__device__ __forceinline__ float2 cmul(float2 a, float2 b) {
    return make_float2(a.x * b.x - a.y * b.y, a.x * b.y + a.y * b.x);
}

__global__ void __launch_bounds__(TPB, 1)
qsim_kernel(const float* __restrict__ x, const float* __restrict__ wts,
            float* __restrict__ out, Params P)
{
    extern __shared__ float smemf[];          // [0,16384): re   [16384,32768): im
    __shared__ float4 gates4[NGATES];
    __shared__ float2 tabA[128], tabB[128];
    __shared__ float  red[TPB / 32];

    const int tid = threadIdx.x;
    const int b   = blockIdx.x;
    const u32 sbase = (u32)__cvta_generic_to_shared(smemf);

    // ---- build SU(2) gates ----
    if (tid < NGATES) {
        int l = tid / NQ, w = tid % NQ;
        const float* ww = wts + tid * 3;
        float phi = ww[0], th = ww[1], om = ww[2];
        float stt, ct, sA, cA, sB, cB;
        sincosf(0.5f * th, &stt, &ct);
        sincosf(0.5f * (phi + om), &sA, &cA);
        sincosf(0.5f * (phi - om), &sB, &cB);
        float2 al = make_float2(ct * cA, -ct * sA);
        float2 be = make_float2(stt * cB, -stt * sB);
        if (l == 0) {
            float s, c;
            sincosf(0.5f * x[b * NQ + w], &s, &c);
            float2 aX = make_float2(c, 0.f), bX = make_float2(0.f, -s);
            float2 cbe = make_float2(be.x, -be.y);
            float2 cal = make_float2(al.x, -al.y);
            float2 t1 = cmul(al, aX), t2 = cmul(cbe, bX);
            float2 aG = make_float2(t1.x - t2.x, t1.y - t2.y);
            float2 t3 = cmul(be, aX), t4 = cmul(cal, bX);
            float2 bG = make_float2(t3.x + t4.x, t3.y + t4.y);
            al = aG; be = bG;
        }
        gates4[tid] = make_float4(al.x, al.y, be.x, be.y);
    }
    __syncthreads();

    // ---- layer 0 as product state ----
    if (tid < 128) {
        float2 a = make_float2(1.f, 0.f);
        #pragma unroll
        for (int w = 0; w < 7; w++) {
            float4 g = gates4[w];
            float2 sel = ((tid >> w) & 1) ? make_float2(g.z, g.w)
                                          : make_float2(g.x, g.y);
            a = cmul(a, sel);
        }
        tabA[tid] = a;
    } else if (tid < 256) {
        int t = tid - 128;
        float2 a = make_float2(1.f, 0.f);
        #pragma unroll
        for (int w = 0; w < 7; w++) {
            float4 g = gates4[7 + w];
            float2 sel = ((t >> w) & 1) ? make_float2(g.z, g.w)
                                        : make_float2(g.x, g.y);
            a = cmul(a, sel);
        }
        tabB[t] = a;
    }
    __syncthreads();

    for (int i = tid; i < NSTATE; i += TPB) {
        float2 c = cmul(tabA[i & 127], tabB[i >> 7]);
        smemf[i]          = c.x;
        smemf[NSTATE + i] = c.y;
    }
    __syncthreads();

    // ---- 15 passes ----
    #pragma unroll 1
    for (int ps = 0; ps < NPASSES; ps++) {
        const PassP& pp = P.p[ps];
        if (pp.nw == 5) apply_pass5s(sbase, gates4, pp, tid);
        else            apply_pass4(sbase, gates4, pp, tid);
        __syncthreads();
    }

    // ---- <Z_0> ----
    float acc = 0.f;
    const u32 rz = P.rz;
    for (int i = tid; i < NSTATE; i += TPB) {
        float re = smemf[i], im = smemf[NSTATE + i];
        float pr = fmaf(re, re, im * im);
        acc += (__popc((u32)i & rz) & 1) ? -pr : pr;
    }
    #pragma unroll
    for (int off = 16; off; off >>= 1)
        acc += __shfl_down_sync(0xffffffffu, acc, off);
    if ((tid & 31) == 0) red[tid >> 5] = acc;
    __syncthreads();
    if (tid == 0) {
        float s = 0.f;
        #pragma unroll
        for (int wgi = 0; wgi < TPB / 32; wgi++) s += red[wgi];
        out[b] = s;
    }
}

// ---------------- host precompute ----------------
static inline int ctz32(u32 v) {
    int c = 0; while (!(v & 1u)) { v >>= 1; c++; } return c;
}

static int rankN(const u32* F, int n) {
    u32 a[5];
    for (int i = 0; i < n; i++) a[i] = F[i];
    int r = 0;
    for (int bit = 0; bit < 5; bit++) {
        int s = -1;
        for (int i = r; i < n; i++) if ((a[i] >> bit) & 1u) { s = i; break; }
        if (s < 0) continue;
        u32 t = a[s]; a[s] = a[r]; a[r] = t;
        for (int i = 0; i < n; i++)
            if (i != r && ((a[i] >> bit) & 1u)) a[i] ^= a[r];
        r++;
    }
    return r;
}

static bool dfsGen(const u32* vb, const u32* cm, const int* lim,
                   u32* F, u32* A, int depth) {
    if (depth == 5) return true;
    for (int a = 0; a < lim[depth]; a++) {
        F[depth] = (vb[depth] ^ cm[a]) & 31u;
        if (rankN(F, depth + 1) == depth + 1) {
            A[depth] = (u32)a;
            if (dfsGen(vb, cm, lim, F, A, depth + 1)) return true;
        }
    }
    return false;
}

static void sort_ints(int* a, int n) {
    for (int i = 0; i < n; i++)
        for (int j = i + 1; j < n; j++)
            if (a[j] < a[i]) { int t = a[i]; a[i] = a[j]; a[j] = t; }
}

// ---- NW=4 unsplit pass (wires wsel[0..3]) ----
static void fill_pass4h(PassP& ps, const u32* col, const u32* row,
                        const int* wsel, int l) {
    const int nw = 4;
    u32 m[4], cm[32];
    for (int i = 0; i < nw; i++) {
        ps.r[i] = row[wsel[i]];
        m[i]    = col[wsel[i]];
        ps.g[i] = (unsigned char)(l * NQ + wsel[i]);
    }
    ps.r[4] = 0;
    for (int i = nw; i < 8; i++) ps.g[i] = 0;
    for (int j = 0; j < 32; j++) cm[j] = 0;
    for (int j = 0; j < 16; j++) {
        u32 c = 0;
        for (int i = 0; i < nw; i++) if ((j >> i) & 1) c ^= m[i];
        cm[j] = c;
    }
    for (int j = 0; j < 32; j++) ps.cmb[j] = cm[j] << 2;

    u32 redm[4]; int pv[4];
    for (int i = 0; i < nw; i++) {
        u32 v = m[i];
        for (int j = 0; j < i; j++)
            if ((v >> pv[j]) & 1u) v ^= redm[j];
        pv[i] = ctz32(v);
        redm[i] = v;
    }
    sort_ints(pv, nw);
    ps.nw = nw;

    int bestd = -1;
    int lim[5] = {16, 16, 16, 16, 16};
    for (int d = 0; d < NQ; d++) {
        bool ispv = false;
        for (int i = 0; i < nw; i++) if (pv[i] == d) ispv = true;
        if (ispv) continue;
        if (bestd < 0) bestd = d;
        int ep[5]; { int t[5]; for (int i = 0; i < nw; i++) t[i] = pv[i]; t[nw] = d;
                     sort_ints(t, 5); for (int i = 0; i < 5; i++) ep[i] = t[i]; }
        u32 vb[5], F[5], A[5];
        for (int b = 0; b < 5; b++) {
            int pos = b;
            for (int i = 0; i < 5; i++) if (ep[i] <= pos) pos++;
            u32 v = (pos < 32) ? (1u << pos) : 0u;
            if (v) for (int k = 0; k < nw; k++)
                if ((ps.r[k] >> pos) & 1u) v ^= m[k];
            vb[b] = v;
        }
        if (dfsGen(vb, cm, lim, F, A, 0)) {
            for (int i = 0; i < 5; i++) ps.ep[i] = (signed char)ep[i];
            for (int i = 5; i < 8; i++) ps.ep[i] = 0;
            for (int i = 0; i < 5; i++) ps.Arl[i] = (unsigned char)A[i];
            for (int i = 5; i < 8; i++) ps.Arl[i] = 0;
            ps.ddb = 4u << d;
            u32 f = 0;
            for (int k = 0; k < nw; k++)
                if ((ps.r[k] >> d) & 1u) f |= 1u << k;
            ps.f = f;
            return;
        }
    }
    // fallback: conflicted but correct
    int ep[5]; { int t[5]; for (int i = 0; i < nw; i++) t[i] = pv[i]; t[nw] = bestd;
                 sort_ints(t, 5); for (int i = 0; i < 5; i++) ep[i] = t[i]; }
    for (int i = 0; i < 5; i++) ps.ep[i] = (signed char)ep[i];
    for (int i = 5; i < 8; i++) ps.ep[i] = 0;
    for (int i = 0; i < 8; i++) ps.Arl[i] = 0;
    ps.ddb = 4u << bestd;
    u32 f = 0;
    for (int k = 0; k < nw; k++)
        if ((ps.r[k] >> bestd) & 1u) f |= 1u << k;
    ps.f = f;
}

// ---- NW=5 split pass (wires wsel[0..4]) ----
static bool try_fill5s(PassP& ps, const u32* mm, const u32* rr_, const int* gid,
                       const int* pv, int d, int ks, bool need_rank) {
    if ((rr_[ks] >> d) & 1u) return false;        // split gate duo-flip must be 0
    u32 om[5], orow[5]; int og[5]; int idx = 0;
    for (int i = 0; i < 5; i++) if (i != ks) { om[idx] = mm[i]; orow[idx] = rr_[i]; og[idx] = gid[i]; idx++; }
    om[4] = mm[ks]; orow[4] = rr_[ks]; og[4] = gid[ks];
    if (need_rank && (om[4] & 31u) == 0) return false;  // role bank column must be nonzero

    u32 cm[32];
    for (int j = 0; j < 32; j++) {
        u32 c = 0;
        for (int i = 0; i < 5; i++) if ((j >> i) & 1) c ^= om[i];
        cm[j] = c;
    }
    int ep[6]; { int t[6]; for (int i = 0; i < 5; i++) t[i] = pv[i]; t[5] = d;
                 sort_ints(t, 6); for (int i = 0; i < 6; i++) ep[i] = t[i]; }
    u32 vb[5], F[5], A[5];
    vb[0] = om[4] & 31u;                           // role column (no fold correction)
    for (int b = 1; b < 5; b++) {
        int pos = b - 1;                           // duoid bit b-1
        for (int i = 0; i < 6; i++) if (ep[i] <= pos) pos++;
        u32 v = (pos < 32) ? (1u << pos) : 0u;
        if (v) for (int k = 0; k < 5; k++)
            if ((orow[k] >> pos) & 1u) v ^= om[k];
        vb[b] = v;
    }
    if (need_rank) {
        int lim[5] = {1, 32, 32, 32, 32};          // Arl[0] forced to 0
        if (!dfsGen(vb, cm, lim, F, A, 0)) return false;
    } else {
        for (int i = 0; i < 5; i++) A[i] = 0;
    }
    for (int j = 0; j < 32; j++) ps.cmb[j] = cm[j] << 2;
    for (int k = 0; k < 5; k++) ps.r[k] = orow[k];
    for (int k = 0; k < 5; k++) ps.g[k] = (unsigned char)og[k];
    for (int i = 5; i < 8; i++) ps.g[i] = 0;
    for (int i = 0; i < 6; i++) ps.ep[i] = (signed char)ep[i];
    for (int i = 6; i < 8; i++) ps.ep[i] = 0;
    for (int b = 0; b < 5; b++) ps.Arl[b] = (unsigned char)A[b];
    for (int i = 5; i < 8; i++) ps.Arl[i] = 0;
    u32 f = 0;
    for (int k = 0; k < 4; k++)
        if ((orow[k] >> d) & 1u) f |= 1u << k;     // bit4 == 0 by construction
    ps.f = f;
    ps.ddb = 4u << d;
    ps.nw = 5;
    return true;
}

static void fill_pass5h(PassP& ps, const u32* col, const u32* row,
                        const int* wsel, int l) {
    u32 mm[5], rr_[5]; int gid[5];
    for (int i = 0; i < 5; i++) {
        mm[i] = col[wsel[i]]; rr_[i] = row[wsel[i]]; gid[i] = l * NQ + wsel[i];
    }
    u32 redm[5]; int pv[5];
    for (int i = 0; i < 5; i++) {
        u32 v = mm[i];
        for (int j = 0; j < i; j++)
            if ((v >> pv[j]) & 1u) v ^= redm[j];
        pv[i] = ctz32(v);
        redm[i] = v;
    }
    sort_ints(pv, 5);

    for (int d = 0; d < NQ; d++) {
        bool ispv = false;
        for (int i = 0; i < 5; i++) if (pv[i] == d) ispv = true;
        if (ispv) continue;
        for (int ks = 0; ks < 5; ks++)
            if (try_fill5s(ps, mm, rr_, gid, pv, d, ks, true)) return;
    }
    // fallback: correctness-preserving (no stagger), first valid (d, ks)
    for (int d = 0; d < NQ; d++) {
        bool ispv = false;
        for (int i = 0; i < 5; i++) if (pv[i] == d) ispv = true;
        if (ispv) continue;
        for (int ks = 0; ks < 5; ks++)
            if (try_fill5s(ps, mm, rr_, gid, pv, d, ks, false)) return;
    }
}

extern "C" void kernel_launch(void* const* d_in, const int* in_sizes, int n_in,
                              void* d_out, int out_size) {
    const float* x   = (const float*)d_in[0];
    const float* wts = (const float*)d_in[1];
    float*       out = (float*)d_out;
    const int B = in_sizes[0] / NQ;

    Params P;
    u32 col[NQ], row[NQ];
    for (int i = 0; i < NQ; i++) { col[i] = 1u << i; row[i] = 1u << i; }

    // layer 0 handled by product-state init; absorb its CNOT ring first
    {
        int r = 1;
        for (int w = 0; w < NQ; w++) {
            int c = w, t = (w + r) % NQ;
            col[c] ^= col[t];
            row[t] ^= row[c];
        }
    }

    int pi = 0;
    for (int l = 1; l < NLAYERS; l++) {
        static const int g5a[5] = {0,1,2,3,4};
        static const int g5b[5] = {5,6,7,8,9};
        static const int g4c[4] = {10,11,12,13};
        fill_pass5h(P.p[pi++], col, row, g5a, l);
        fill_pass5h(P.p[pi++], col, row, g5b, l);
        fill_pass4h(P.p[pi++], col, row, g4c, l);

        int r = (l % (NQ - 1)) + 1;
        for (int w = 0; w < NQ; w++) {
            int c = w, t = (w + r) % NQ;
            col[c] ^= col[t];
            row[t] ^= row[c];
        }
    }
    P.rz = row[0];

    const size_t smem = 2 * NSTATE * sizeof(float);   // 131072 B
    cudaFuncSetAttribute(qsim_kernel, cudaFuncAttributeMaxDynamicSharedMemorySize,
                         (int)smem);
    qsim_kernel<<<B, TPB, smem>>>(x, wts, out, P);
}